// round 4
// baseline (speedup 1.0000x reference)
#include <cuda_runtime.h>
#include <math.h>

#define N_NODES 50000
#define N_EDGES 800000
#define DIM 128
#define CAP 64

typedef unsigned long long u64;

// Scratch (allocation-free rule: __device__ globals)
__device__ float g_support[N_NODES * DIM];       // 25.6 MB
__device__ int   g_cnt[N_NODES];
__device__ int2  g_bucket[N_NODES * CAP];        // packed (col, val)
__device__ int   g_ovf[N_EDGES];                 // overflow edge ids (expected empty)
__device__ int   g_ovf_cnt;

__device__ __forceinline__ u64 pk2(float a, float b) {
    u64 r; asm("mov.b64 %0, {%1,%2};" : "=l"(r) : "f"(a), "f"(b)); return r;
}
__device__ __forceinline__ u64 ffma2(u64 a, u64 b, u64 c) {
    u64 d; asm("fma.rn.f32x2 %0, %1, %2, %3;" : "=l"(d) : "l"(a), "l"(b), "l"(c)); return d;
}

// ---------------- K0: zero counters ----------------
__global__ void k_zero() {
    int i = blockIdx.x * blockDim.x + threadIdx.x;
    if (i < N_NODES) g_cnt[i] = 0;
    if (i == 0) g_ovf_cnt = 0;
}

// ---------------- K1: fused GEMM (FFMA2) + edge bucketing ----------------
// gemm blocks: 64-row tile, 128 threads, 8 rows x 8 cols per thread, packed f32x2.
// bucket blocks: grid-stride edge scatter into per-row buckets.
#define GEMM_BLOCKS 782          // ceil(50000/64)
#define BUCKET_BLOCKS 1024

__global__ __launch_bounds__(128) void k_fused(const float* __restrict__ X,
                                               const float* __restrict__ W,
                                               const int* __restrict__ rows,
                                               const int* __restrict__ cols,
                                               const float* __restrict__ vals) {
    if (blockIdx.x >= GEMM_BLOCKS) {
        // ------------- bucket part -------------
        int b = blockIdx.x - GEMM_BLOCKS;
        for (int e = b * 128 + threadIdx.x; e < N_EDGES; e += BUCKET_BLOCKS * 128) {
            int r = rows[e];
            int pos = atomicAdd(&g_cnt[r], 1);
            if (pos < CAP) {
                g_bucket[r * CAP + pos] = make_int2(cols[e], __float_as_int(vals[e]));
            } else {
                int o = atomicAdd(&g_ovf_cnt, 1);
                g_ovf[o] = e;   // correct fallback path (expected empty)
            }
        }
        return;
    }

    // ------------- gemm part -------------
    __shared__ u64 Wp[32 * 64];     // [k][col-pair], packed (w0,w1)   16 KB
    __shared__ u64 Xd[64 * 33];     // [row][k] duplicated (x,x), pad  16.9 KB

    const int tid  = threadIdx.x;       // 0..127
    const int rowg = tid & 7;           // 0..7  (lane-varying -> padded Xd, no conflicts)
    const int colg = tid >> 3;          // 0..15 (4 distinct per warp -> Wp, no conflicts)
    const int rbase = blockIdx.x * 64;

    u64 acc[8][4];
    #pragma unroll
    for (int m = 0; m < 8; m++)
        #pragma unroll
        for (int j = 0; j < 4; j++) acc[m][j] = 0ull;

    for (int kc = 0; kc < 128; kc += 32) {
        // W chunk: 32 k-rows x 128 cols = 32x32 float4 = 1024 float4, 8 per thread
        #pragma unroll
        for (int p = 0; p < 8; p++) {
            int f = tid + p * 128;
            int k = f >> 5, q = f & 31;          // FIXED: 32 float4 per k-row
            float4 w = ((const float4*)W)[(kc + k) * 32 + q];
            Wp[k * 64 + q * 2 + 0] = pk2(w.x, w.y);
            Wp[k * 64 + q * 2 + 1] = pk2(w.z, w.w);
        }
        // X chunk: 64 rows x 32 k = 512 float4, 4 per thread (duplicated stores)
        #pragma unroll
        for (int p = 0; p < 4; p++) {
            int f = tid + p * 128;
            int r = f >> 3, q = f & 7;
            int row = rbase + r;
            float4 v = make_float4(0.f, 0.f, 0.f, 0.f);
            if (row < N_NODES) v = ((const float4*)X)[row * 32 + (kc >> 2) + q];
            Xd[r * 33 + q * 4 + 0] = pk2(v.x, v.x);
            Xd[r * 33 + q * 4 + 1] = pk2(v.y, v.y);
            Xd[r * 33 + q * 4 + 2] = pk2(v.z, v.z);
            Xd[r * 33 + q * 4 + 3] = pk2(v.w, v.w);
        }
        __syncthreads();

        #pragma unroll 8
        for (int k = 0; k < 32; k++) {
            u64 w0 = Wp[k * 64 + colg * 4 + 0];
            u64 w1 = Wp[k * 64 + colg * 4 + 1];
            u64 w2 = Wp[k * 64 + colg * 4 + 2];
            u64 w3 = Wp[k * 64 + colg * 4 + 3];
            #pragma unroll
            for (int m = 0; m < 8; m++) {
                u64 xx = Xd[(rowg + 8 * m) * 33 + k];
                acc[m][0] = ffma2(xx, w0, acc[m][0]);
                acc[m][1] = ffma2(xx, w1, acc[m][1]);
                acc[m][2] = ffma2(xx, w2, acc[m][2]);
                acc[m][3] = ffma2(xx, w3, acc[m][3]);
            }
        }
        __syncthreads();
    }

    u64* sup64 = (u64*)g_support;
    #pragma unroll
    for (int m = 0; m < 8; m++) {
        int row = rbase + rowg + 8 * m;
        if (row < N_NODES) {
            #pragma unroll
            for (int j = 0; j < 4; j++)
                sup64[row * 64 + colg * 4 + j] = acc[m][j];
        }
    }
}

// ---------------- K2: warp-per-row aggregate + inline overflow + bias/ELU ----
__global__ __launch_bounds__(256) void k_agg(const float* __restrict__ X,
                                             const float* __restrict__ alpha,
                                             const float* __restrict__ bias,
                                             const int* __restrict__ rows,
                                             const int* __restrict__ cols,
                                             const float* __restrict__ vals,
                                             float* __restrict__ out) {
    int row  = (blockIdx.x * blockDim.x + threadIdx.x) >> 5;
    int lane = threadIdx.x & 31;
    if (row >= N_NODES) return;

    float a0 = alpha[0], a1 = alpha[1];
    float mx = fmaxf(a0, a1);
    float e0 = __expf(a0 - mx), e1 = __expf(a1 - mx);
    float g0 = e0 / (e0 + e1);          // gate for agg
    float g1 = e1 / (e0 + e1);          // gate for residual input

    float4 x4 = ((const float4*)X)[row * 32 + lane];
    float4 acc = make_float4(g1 * x4.x, g1 * x4.y, g1 * x4.z, g1 * x4.w);

    int nraw = g_cnt[row];
    int n = nraw > CAP ? CAP : nraw;
    const int2* bk = g_bucket + row * CAP;
    const float4* sup4 = (const float4*)g_support;

    for (int base = 0; base < n; base += 32) {
        int2 meta = make_int2(0, 0);
        if (base + lane < n) meta = bk[base + lane];
        int cnt = n - base; if (cnt > 32) cnt = 32;
        int c4 = (cnt + 3) & ~3;
        for (int j = 0; j < c4; j += 4) {
            int   c0 = __shfl_sync(0xffffffffu, meta.x, j + 0);
            int   c1 = __shfl_sync(0xffffffffu, meta.x, j + 1);
            int   c2 = __shfl_sync(0xffffffffu, meta.x, j + 2);
            int   c3 = __shfl_sync(0xffffffffu, meta.x, j + 3);
            float v0 = g0 * __int_as_float(__shfl_sync(0xffffffffu, meta.y, j + 0));
            float v1 = g0 * __int_as_float(__shfl_sync(0xffffffffu, meta.y, j + 1));
            float v2 = g0 * __int_as_float(__shfl_sync(0xffffffffu, meta.y, j + 2));
            float v3 = g0 * __int_as_float(__shfl_sync(0xffffffffu, meta.y, j + 3));
            float4 s0 = sup4[c0 * 32 + lane];
            float4 s1 = sup4[c1 * 32 + lane];
            float4 s2 = sup4[c2 * 32 + lane];
            float4 s3 = sup4[c3 * 32 + lane];
            acc.x += v0 * s0.x; acc.y += v0 * s0.y; acc.z += v0 * s0.z; acc.w += v0 * s0.w;
            acc.x += v1 * s1.x; acc.y += v1 * s1.y; acc.z += v1 * s1.z; acc.w += v1 * s1.w;
            acc.x += v2 * s2.x; acc.y += v2 * s2.y; acc.z += v2 * s2.z; acc.w += v2 * s2.w;
            acc.x += v3 * s3.x; acc.y += v3 * s3.y; acc.z += v3 * s3.z; acc.w += v3 * s3.w;
        }
    }

    // inline overflow fallback: scan global overflow list (expected 0 entries)
    if (nraw > CAP) {
        int nov = g_ovf_cnt;
        for (int i = 0; i < nov; i++) {
            int e = g_ovf[i];
            if (rows[e] == row) {
                int c = cols[e];
                float v = g0 * vals[e];
                float4 s = sup4[c * 32 + lane];
                acc.x += v * s.x; acc.y += v * s.y; acc.z += v * s.z; acc.w += v * s.w;
            }
        }
    }

    // bias + ELU (always; all contributions are in-register)
    float4 b = ((const float4*)bias)[lane];
    acc.x += b.x; acc.y += b.y; acc.z += b.z; acc.w += b.w;
    acc.x = acc.x > 0.f ? acc.x : expm1f(acc.x);
    acc.y = acc.y > 0.f ? acc.y : expm1f(acc.y);
    acc.z = acc.z > 0.f ? acc.z : expm1f(acc.z);
    acc.w = acc.w > 0.f ? acc.w : expm1f(acc.w);
    ((float4*)out)[row * 32 + lane] = acc;
}

extern "C" void kernel_launch(void* const* d_in, const int* in_sizes, int n_in,
                              void* d_out, int out_size) {
    const float* X     = (const float*)d_in[0];   // inputs  [50000,128]
    const float* W     = (const float*)d_in[1];   // weight  [128,128]
    const float* bias  = (const float*)d_in[2];   // bias    [128]
    const float* alpha = (const float*)d_in[3];   // alpha   [2]
    const float* vals  = (const float*)d_in[4];   // adj_vals [800000]
    const int*   rows  = (const int*)d_in[5];     // adj_rows [800000]
    const int*   cols  = (const int*)d_in[6];     // adj_cols [800000]
    float* out = (float*)d_out;

    k_zero <<<(N_NODES + 255) / 256, 256>>>();
    k_fused<<<GEMM_BLOCKS + BUCKET_BLOCKS, 128>>>(X, W, rows, cols, vals);
    k_agg  <<<(N_NODES + 7) / 8, 256>>>(X, alpha, bias, rows, cols, vals, out);
}